// round 5
// baseline (speedup 1.0000x reference)
#include <cuda_runtime.h>

#define FULL 0xffffffffu
typedef unsigned long long ull;

constexpr int   N_SAMP = 64;
constexpr int   RAYS_TOTAL = 4 * 64 * 64;   // 16384
constexpr float NEARF = 2.0f, FARF = 6.0f;
constexpr int   RPB = 8;                    // rays (warps) per block

__device__ __forceinline__ ull pack2(float lo, float hi) {
    ull r; asm("mov.b64 %0,{%1,%2};" : "=l"(r) : "f"(lo), "f"(hi)); return r;
}
__device__ __forceinline__ void unpack2(ull v, float& lo, float& hi) {
    asm("mov.b64 {%0,%1},%2;" : "=f"(lo), "=f"(hi) : "l"(v));
}
__device__ __forceinline__ ull fma2(ull a, ull b, ull c) {
    ull d; asm("fma.rn.f32x2 %0,%1,%2,%3;" : "=l"(d) : "l"(a), "l"(b), "l"(c)); return d;
}
__device__ __forceinline__ ull relu2(ull v) {
    float lo, hi; unpack2(v, lo, hi);
    return pack2(fmaxf(lo, 0.f), fmaxf(hi, 0.f));
}

// ---- weights: W1/b1/b2 in __constant__ (LDC port), W2t in __device__ global (LDG/L1 port) ----
// staging layout (ulonglong2 units):
//   [0..15]   w1a : W1 row-x pair packing ([q].x = units{4q,4q+1}, .y = {4q+2,4q+3})
//   [16..31]  w1b : W1 row-y
//   [32..47]  w1c : W1 row-z
//   [48..63]  bb1 : b1
//   [64..127] w2t : entry 4q+c: .x = {W2[4q][c],W2[4q+1][c]}, .y = {W2[4q+2][c],W2[4q+3][c]}
//   [128]     b2  : {(b2_0,b2_1),(b2_2,b2_3)}
__constant__ ulonglong2 cAll[129];
__device__   ulonglong2 g_stage[129];

__global__ void pack_weights(const float* __restrict__ W1, const float* __restrict__ b1f,
                             const float* __restrict__ W2, const float* __restrict__ b2f)
{
    const int t = threadIdx.x;   // 0..63
    float* s = (float*)g_stage;
    s[t]       = W1[t];          // row x  -> floats [0..63]
    s[64 + t]  = W1[64 + t];     // row y  -> [64..127]
    s[128 + t] = W1[128 + t];    // row z  -> [128..191]
    s[192 + t] = b1f[t];         // b1     -> [192..255]
    // w2t: 128 ull entries at ull offset 128 (float offset 256)
    ull* w2t = ((ull*)g_stage) + 128;
    int e = t;
    #pragma unroll
    for (int k = 0; k < 2; ++k, e += 64) {
        const int ent = e >> 1, half = e & 1;   // ent = 4q+c
        const int q = ent >> 2, c = ent & 3;
        const int u0 = 4 * q + 2 * half;
        w2t[e] = pack2(W2[u0 * 4 + c], W2[(u0 + 1) * 4 + c]);
    }
    if (t == 0) {
        s[512] = b2f[0]; s[513] = b2f[1]; s[514] = b2f[2]; s[515] = b2f[3];
    }
}

// # elements < x in sorted a[0..63]
__device__ __forceinline__ int count_lt(const float* __restrict__ a, float x) {
    int lo = 0, hi = 64;
    #pragma unroll
    for (int it = 0; it < 7; ++it) {
        if (lo < hi) { int m = (lo + hi) >> 1; if (a[m] < x) lo = m + 1; else hi = m; }
    }
    return lo;
}
// # elements <= x in sorted a[0..63]
__device__ __forceinline__ int count_le(const float* __restrict__ a, float x) {
    int lo = 0, hi = 64;
    #pragma unroll
    for (int it = 0; it < 7; ++it) {
        if (lo < hi) { int m = (lo + hi) >> 1; if (a[m] <= x) lo = m + 1; else hi = m; }
    }
    return lo;
}

// Tiny MLP at TWO points, fully f32x2-packed.
// Layer-1 weights from __constant__ (LDC port); layer-2 weights via __ldg (L1 port).
__device__ __forceinline__ void field_eval2(
    float px0, float py0, float pz0,
    float px1, float py1, float pz1,
    float4 b2v,
    float& sg0, float& r0, float& g0, float& b0,
    float& sg1, float& r1, float& g1, float& b1)
{
    const ulonglong2* __restrict__ w1a = cAll;
    const ulonglong2* __restrict__ w1b = cAll + 16;
    const ulonglong2* __restrict__ w1c = cAll + 32;
    const ulonglong2* __restrict__ bb1 = cAll + 48;
    const ulonglong2* __restrict__ w2t = g_stage + 64;   // global, broadcast L1 hits

    const ull X0 = pack2(px0, px0), Y0 = pack2(py0, py0), Z0 = pack2(pz0, pz0);
    const ull X1 = pack2(px1, px1), Y1 = pack2(py1, py1), Z1 = pack2(pz1, pz1);
    ull a00 = pack2(b2v.x, 0.f), a01 = pack2(b2v.y, 0.f);
    ull a02 = pack2(b2v.z, 0.f), a03 = pack2(b2v.w, 0.f);
    ull a10 = pack2(b2v.x, 0.f), a11 = pack2(b2v.y, 0.f);
    ull a12 = pack2(b2v.z, 0.f), a13 = pack2(b2v.w, 0.f);
    #pragma unroll
    for (int q = 0; q < 16; ++q) {
        const ulonglong2 A = w1a[q], Bw = w1b[q], C = w1c[q], D = bb1[q];
        ull h0a = fma2(X0, A.x, fma2(Y0, Bw.x, fma2(Z0, C.x, D.x)));
        ull h0b = fma2(X0, A.y, fma2(Y0, Bw.y, fma2(Z0, C.y, D.y)));
        ull h1a = fma2(X1, A.x, fma2(Y1, Bw.x, fma2(Z1, C.x, D.x)));
        ull h1b = fma2(X1, A.y, fma2(Y1, Bw.y, fma2(Z1, C.y, D.y)));
        h0a = relu2(h0a); h0b = relu2(h0b);
        h1a = relu2(h1a); h1b = relu2(h1b);
        const ulonglong2 T0 = __ldg(&w2t[4 * q + 0]);
        const ulonglong2 T1 = __ldg(&w2t[4 * q + 1]);
        const ulonglong2 T2 = __ldg(&w2t[4 * q + 2]);
        const ulonglong2 T3 = __ldg(&w2t[4 * q + 3]);
        a00 = fma2(h0a, T0.x, a00); a00 = fma2(h0b, T0.y, a00);
        a01 = fma2(h0a, T1.x, a01); a01 = fma2(h0b, T1.y, a01);
        a02 = fma2(h0a, T2.x, a02); a02 = fma2(h0b, T2.y, a02);
        a03 = fma2(h0a, T3.x, a03); a03 = fma2(h0b, T3.y, a03);
        a10 = fma2(h1a, T0.x, a10); a10 = fma2(h1b, T0.y, a10);
        a11 = fma2(h1a, T1.x, a11); a11 = fma2(h1b, T1.y, a11);
        a12 = fma2(h1a, T2.x, a12); a12 = fma2(h1b, T2.y, a12);
        a13 = fma2(h1a, T3.x, a13); a13 = fma2(h1b, T3.y, a13);
    }
    float lo, hi;
    unpack2(a00, lo, hi); sg0 = lo + hi;
    unpack2(a01, lo, hi); r0 = __fdividef(1.f, 1.f + __expf(-(lo + hi)));
    unpack2(a02, lo, hi); g0 = __fdividef(1.f, 1.f + __expf(-(lo + hi)));
    unpack2(a03, lo, hi); b0 = __fdividef(1.f, 1.f + __expf(-(lo + hi)));
    unpack2(a10, lo, hi); sg1 = lo + hi;
    unpack2(a11, lo, hi); r1 = __fdividef(1.f, 1.f + __expf(-(lo + hi)));
    unpack2(a12, lo, hi); g1 = __fdividef(1.f, 1.f + __expf(-(lo + hi)));
    unpack2(a13, lo, hi); b1 = __fdividef(1.f, 1.f + __expf(-(lo + hi)));
}

__global__ void __launch_bounds__(RPB * 32, 4)
nerf_kernel(const float* __restrict__ ro,   const float* __restrict__ rdi,
            const float* __restrict__ tform, const float* __restrict__ noise,
            const float* __restrict__ usmp,
            float* __restrict__ orgb, float* __restrict__ odep, float* __restrict__ omsk)
{
    __shared__ float  sZ [RPB][128];   // coarse z [0..63], then all-sorted z
    __shared__ float  sSg[RPB][128];   // cdf [0..62], sorted fine [64..127], then sorted sigma
    __shared__ float  sC [RPB][384];   // sorted rgb
    __shared__ float  sWt[RPB][64];    // coarse compositing weights

    const int tid = threadIdx.x;
    const int wrp = tid >> 5, lane = tid & 31;
    const int ray = blockIdx.x * RPB + wrp;
    float* zw  = sZ[wrp];
    float* sgw = sSg[wrp];
    float* sf  = sgw + 64;     // sorted fine z
    float* cw  = sC[wrp];
    float* wtw = sWt[wrp];

    float b20, b21, b22, b23;
    unpack2(cAll[128].x, b20, b21);
    unpack2(cAll[128].y, b22, b23);
    const float4 b2v = make_float4(b20, b21, b22, b23);

    const int bidx = ray >> 12;

    const float ox = ro[ray * 3 + 0], oy = ro[ray * 3 + 1], oz = ro[ray * 3 + 2];
    float dx = rdi[ray * 3 + 0], dy = rdi[ray * 3 + 1], dz = rdi[ray * 3 + 2];
    const float rinvn = rsqrtf(dx * dx + dy * dy + dz * dz);
    dx *= rinvn; dy *= rinvn; dz *= rinvn;

    // -------- coarse stratified z (sorted by construction) --------
    const float2 nzp = ((const float2*)(noise + ray * N_SAMP))[lane];
    const int i0 = 2 * lane, i1 = i0 + 1;
    const float z0 = NEARF + (FARF - NEARF) * (((float)i0 + nzp.x) * (1.f / 64.f));
    const float z1 = NEARF + (FARF - NEARF) * (((float)i1 + nzp.y) * (1.f / 64.f));
    zw[i0] = z0; zw[i1] = z1;
    __syncwarp();

    // -------- coarse MLP --------
    float sg0, cr0, cg0, cb0, sg1, cr1, cg1, cb1;
    field_eval2(fmaf(dx, z0, ox), fmaf(dy, z0, oy), fmaf(dz, z0, oz),
                fmaf(dx, z1, ox), fmaf(dy, z1, oy), fmaf(dz, z1, oz),
                b2v, sg0, cr0, cg0, cb0, sg1, cr1, cg1, cb1);

    // -------- coarse compositing weights (warp multiplicative scan) --------
    const float d0 = z1 - z0;
    const float znx = (lane < 31) ? zw[i1 + 1] : 0.f;
    const float d1 = (lane == 31) ? 1e10f : (znx - z1);
    const float e0 = __expf(-fmaxf(sg0, 0.f) * d0);
    const float e1 = __expf(-fmaxf(sg1, 0.f) * d1);
    const float a0 = 1.f - e0, a1 = 1.f - e1;
    const float m0 = 1.f - a0 + 1e-10f, m1 = 1.f - a1 + 1e-10f;
    {
        float v = m0 * m1;
        #pragma unroll
        for (int off = 1; off < 32; off <<= 1) {
            float t = __shfl_up_sync(FULL, v, off);
            if (lane >= off) v *= t;
        }
        float ex = __shfl_up_sync(FULL, v, 1);
        if (lane == 0) ex = 1.f;
        wtw[i0] = a0 * ex;
        wtw[i1] = a1 * ex * m0;
    }
    __syncwarp();

    // -------- pooled pdf -> cdf (63 entries in sgw[0..62]) --------
    {
        float s1 = 0.f, s2 = 0.f;
        if (lane < 31) {
            const int ii = 2 * lane + 1;
            const float wm = wtw[ii - 1], wc = wtw[ii], wp = wtw[ii + 1], wq = wtw[ii + 2];
            s1 = 0.5f * (fmaxf(wm, wc) + fmaxf(wc, wp)) + 0.01f;
            s2 = 0.5f * (fmaxf(wc, wp) + fmaxf(wp, wq)) + 0.01f;
        }
        const float pr = s1 + s2;
        float v = pr;
        #pragma unroll
        for (int off = 1; off < 32; off <<= 1) {
            float t = __shfl_up_sync(FULL, v, off);
            if (lane >= off) v += t;
        }
        const float tot = __shfl_sync(FULL, v, 30);
        const float rv = __fdividef(1.f, tot);
        const float ex = v - pr;
        if (lane == 0) sgw[0] = 0.f;
        if (lane < 31) {
            sgw[2 * lane + 1] = (ex + s1) * rv;
            sgw[2 * lane + 2] = v * rv;
        }
    }
    __syncwarp();

    // -------- inverse-CDF fine samples (2 per lane, unsorted) --------
    const float* uu = usmp + ray * N_SAMP;
    float zs0 = 0.f, zs1 = 0.f;
    #pragma unroll
    for (int k = 0; k < 2; ++k) {
        const float u = uu[lane + 32 * k];
        int lo = 0, hi = 63;                       // searchsorted(cdf[0..62], u, right)
        while (lo < hi) {
            const int mid = (lo + hi) >> 1;
            if (sgw[mid] <= u) lo = mid + 1; else hi = mid;
        }
        const int below = lo - 1;
        const int above = lo < 62 ? lo : 62;
        const float cbv = sgw[below], cav = sgw[above];
        float den = cav - cbv;
        if (den < 1e-5f) den = 1.f;
        const float t  = __fdividef(u - cbv, den);
        const float bb = 0.5f * (zw[below] + zw[below + 1]);
        const float ba = 0.5f * (zw[above] + zw[above + 1]);
        const float zz = fmaf(t, ba - bb, bb);
        if (k == 0) zs0 = zz; else zs1 = zz;
    }

    // -------- bitonic sort of the 64 fine samples (registers + shfl) --------
    float v0 = zs0, v1 = zs1;
    {
        const int e0l = lane, e1l = lane + 32;
        #pragma unroll
        for (int k = 2; k <= 64; k <<= 1) {
            #pragma unroll
            for (int j = k >> 1; j >= 1; j >>= 1) {
                if (j == 32) {
                    const float lo = fminf(v0, v1), hi = fmaxf(v0, v1);
                    v0 = lo; v1 = hi;
                } else {
                    const float t0 = __shfl_xor_sync(FULL, v0, j);
                    const bool keep0 = (((e0l & k) == 0) == ((e0l & j) == 0));
                    v0 = keep0 ? fminf(v0, t0) : fmaxf(v0, t0);
                    const float t1 = __shfl_xor_sync(FULL, v1, j);
                    const bool keep1 = (((e1l & k) == 0) == ((e1l & j) == 0));
                    v1 = keep1 ? fminf(v1, t1) : fmaxf(v1, t1);
                }
            }
        }
    }
    __syncwarp();                                  // cdf reads done before sf write
    sf[lane] = v0;
    sf[lane + 32] = v1;

    // -------- fine MLP at SORTED fine positions --------
    float fs0, fr0, fg0, fb0, fs1, fr1, fg1, fb1;
    field_eval2(fmaf(dx, v0, ox), fmaf(dy, v0, oy), fmaf(dz, v0, oz),
                fmaf(dx, v1, ox), fmaf(dy, v1, oy), fmaf(dz, v1, oz),
                b2v, fs0, fr0, fg0, fb0, fs1, fr1, fg1, fb1);
    __syncwarp();                                  // sf fully written

    // -------- merge ranks: coarse sorted x fine sorted --------
    const int r0 = i0 + count_lt(sf, z0);          // ties: coarse first
    const int r1 = i1 + count_lt(sf, z1);
    const int r2 = lane      + count_le(zw, v0);   // ties: fine after coarse
    const int r3 = lane + 32 + count_le(zw, v1);
    __syncwarp();                                  // all reads done before scatter

    zw[r0] = z0; sgw[r0] = sg0; cw[3 * r0] = cr0; cw[3 * r0 + 1] = cg0; cw[3 * r0 + 2] = cb0;
    zw[r1] = z1; sgw[r1] = sg1; cw[3 * r1] = cr1; cw[3 * r1 + 1] = cg1; cw[3 * r1 + 2] = cb1;
    zw[r2] = v0; sgw[r2] = fs0; cw[3 * r2] = fr0; cw[3 * r2 + 1] = fg0; cw[3 * r2 + 2] = fb0;
    zw[r3] = v1; sgw[r3] = fs1; cw[3 * r3] = fr1; cw[3 * r3 + 1] = fg1; cw[3 * r3 + 2] = fb1;
    __syncwarp();

    // -------- final compositing over 128 sorted samples (4 per lane) --------
    const int p = 4 * lane;
    const float za = zw[p], zb = zw[p + 1], zc = zw[p + 2], zd = zw[p + 3];
    const float zn = (lane < 31) ? zw[p + 4] : 0.f;
    const float sa = sgw[p], sb = sgw[p + 1], sc = sgw[p + 2], sd = sgw[p + 3];
    const float dda = zb - za, ddb = zc - zb, ddc = zd - zc;
    const float ddd = (lane == 31) ? 1e10f : (zn - zd);
    const float ea2 = __expf(-fmaxf(sa, 0.f) * dda);
    const float eb2 = __expf(-fmaxf(sb, 0.f) * ddb);
    const float ec2 = __expf(-fmaxf(sc, 0.f) * ddc);
    const float ed2 = __expf(-fmaxf(sd, 0.f) * ddd);
    const float aa = 1.f - ea2, ab = 1.f - eb2, ac = 1.f - ec2, ad = 1.f - ed2;
    const float ma = 1.f - aa + 1e-10f, mb = 1.f - ab + 1e-10f;
    const float mc = 1.f - ac + 1e-10f, md = 1.f - ad + 1e-10f;
    const float q0 = ma, q1 = ma * mb, q2 = q1 * mc, q3 = q2 * md;
    float v = q3;
    #pragma unroll
    for (int off = 1; off < 32; off <<= 1) {
        float t = __shfl_up_sync(FULL, v, off);
        if (lane >= off) v *= t;
    }
    float E = __shfl_up_sync(FULL, v, 1);
    if (lane == 0) E = 1.f;
    const float wA = aa * E, wB = ab * E * q0, wC = ac * E * q1, wD = ad * E * q2;

    float SW = wA + wB + wC + wD;
    float SZ = wA * za + wB * zb + wC * zc + wD * zd;
    float SR = wA * cw[3 * p]     + wB * cw[3 * (p + 1)]     + wC * cw[3 * (p + 2)]     + wD * cw[3 * (p + 3)];
    float SG = wA * cw[3 * p + 1] + wB * cw[3 * (p + 1) + 1] + wC * cw[3 * (p + 2) + 1] + wD * cw[3 * (p + 3) + 1];
    float SB = wA * cw[3 * p + 2] + wB * cw[3 * (p + 1) + 2] + wC * cw[3 * (p + 2) + 2] + wD * cw[3 * (p + 3) + 2];

    #pragma unroll
    for (int off = 16; off; off >>= 1) {
        SW += __shfl_xor_sync(FULL, SW, off);
        SZ += __shfl_xor_sync(FULL, SZ, off);
        SR += __shfl_xor_sync(FULL, SR, off);
        SG += __shfl_xor_sync(FULL, SG, off);
        SB += __shfl_xor_sync(FULL, SB, off);
    }

    if (lane == 0) {
        orgb[ray * 3 + 0] = SR;
        orgb[ray * 3 + 1] = SG;
        orgb[ray * 3 + 2] = SB;
        const float* Tm = tform + bidx * 16;
        const float vz = dx * Tm[2] + dy * Tm[6] + dz * Tm[10];
        odep[ray] = -vz * SZ;
        omsk[ray] = SW;
    }
}

extern "C" void kernel_launch(void* const* d_in, const int* in_sizes, int n_in,
                              void* d_out, int out_size)
{
    const float* ro    = (const float*)d_in[0];
    const float* rdi   = (const float*)d_in[1];
    const float* tform = (const float*)d_in[2];
    const float* noise = (const float*)d_in[3];
    const float* usmp  = (const float*)d_in[4];
    const float* W1    = (const float*)d_in[5];
    const float* b1    = (const float*)d_in[6];
    const float* W2    = (const float*)d_in[7];
    const float* b2    = (const float*)d_in[8];

    float* out = (float*)d_out;
    float* orgb = out;
    float* odep = out + RAYS_TOTAL * 3;
    float* omsk = odep + RAYS_TOTAL;

    // 1) pack weights into staging buffer (device)
    pack_weights<<<1, 64>>>(W1, b1, W2, b2);
    // 2) staging -> __constant__ (D2D, graph-capturable); w2t stays in global
    void* stage_addr = nullptr;
    cudaGetSymbolAddress(&stage_addr, g_stage);
    cudaMemcpyToSymbolAsync(cAll, stage_addr, sizeof(g_stage), 0,
                            cudaMemcpyDeviceToDevice, 0);
    // 3) main kernel
    dim3 grid(RAYS_TOTAL / RPB);
    dim3 block(RPB * 32);
    nerf_kernel<<<grid, block>>>(ro, rdi, tform, noise, usmp, orgb, odep, omsk);
}

// round 6
// speedup vs baseline: 1.9158x; 1.9158x over previous
#include <cuda_runtime.h>

#define FULL 0xffffffffu
typedef unsigned long long ull;

constexpr int   RAYS_TOTAL = 16384;
constexpr float NEARF = 2.0f, FARF = 6.0f;

__device__ __forceinline__ ull pack2(float lo, float hi) {
    ull r; asm("mov.b64 %0,{%1,%2};" : "=l"(r) : "f"(lo), "f"(hi)); return r;
}
__device__ __forceinline__ void unpack2(ull v, float& lo, float& hi) {
    asm("mov.b64 {%0,%1},%2;" : "=f"(lo), "=f"(hi) : "l"(v));
}
__device__ __forceinline__ ull fma2(ull a, ull b, ull c) {
    ull d; asm("fma.rn.f32x2 %0,%1,%2,%3;" : "=l"(d) : "l"(a), "l"(b), "l"(c)); return d;
}
__device__ __forceinline__ ull mul2(ull a, ull b) {
    ull d; asm("mul.rn.f32x2 %0,%1,%2;" : "=l"(d) : "l"(a), "l"(b)); return d;
}
__device__ __forceinline__ ull relu2(ull v) {
    float lo, hi; unpack2(v, lo, hi);
    return pack2(fmaxf(lo, 0.f), fmaxf(hi, 0.f));
}
__device__ __forceinline__ float sigm(float x) {
    return __fdividef(1.f, 1.f + __expf(-x));
}

// ---- weights ----
// g_stage (also the source for PQ precompute, coalesced LDG):
//   ull[0..31]   W1 row-x pairs (pair j = units 2j,2j+1)
//   ull[32..63]  W1 row-y pairs
//   ull[64..95]  W1 row-z pairs
//   ull[96..127] b1 pairs
//   ull[128..255] w2t: entry e: ent=e>>1(=4q+c),half=e&1,u0=4q+2*half -> pack(W2[u0][c],W2[u0+1][c])
//   float[512..515] b2
// cAll mirrors g_stage; the kernel uses only cAll[64..128] (w2t as ulonglong2 + b2).
__constant__ ulonglong2 cAll[129];
__device__   ulonglong2 g_stage[129];

__global__ void pack_weights(const float* __restrict__ W1, const float* __restrict__ b1f,
                             const float* __restrict__ W2, const float* __restrict__ b2f)
{
    const int t = threadIdx.x;   // 0..63
    float* s = (float*)g_stage;
    s[t]       = W1[t];
    s[64 + t]  = W1[64 + t];
    s[128 + t] = W1[128 + t];
    s[192 + t] = b1f[t];
    ull* w2t = ((ull*)g_stage) + 128;
    int e = t;
    #pragma unroll
    for (int k = 0; k < 2; ++k, e += 64) {
        const int ent = e >> 1, half = e & 1;
        const int q = ent >> 2, c = ent & 3;
        const int u0 = 4 * q + 2 * half;
        w2t[e] = pack2(W2[u0 * 4 + c], W2[(u0 + 1) * 4 + c]);
    }
    if (t == 0) {
        s[512] = b2f[0]; s[513] = b2f[1]; s[514] = b2f[2]; s[515] = b2f[3];
    }
}

// # elements < x in sorted a[0..63]
__device__ __forceinline__ int count_lt(const float* __restrict__ a, float x) {
    int lo = 0, hi = 64;
    #pragma unroll
    for (int it = 0; it < 7; ++it) {
        if (lo < hi) { int m = (lo + hi) >> 1; if (a[m] < x) lo = m + 1; else hi = m; }
    }
    return lo;
}
// # elements <= x in sorted a[0..63]
__device__ __forceinline__ int count_le(const float* __restrict__ a, float x) {
    int lo = 0, hi = 64;
    #pragma unroll
    for (int it = 0; it < 7; ++it) {
        if (lo < hi) { int m = (lo + hi) >> 1; if (a[m] <= x) lo = m + 1; else hi = m; }
    }
    return lo;
}

// inverse-CDF sample: cdf in sgw[0..62], coarse z (bins' endpoints) in zw[0..63]
__device__ __forceinline__ float sample_pdf_one(const float* __restrict__ sgw,
                                                const float* __restrict__ zw, float u)
{
    int lo = 0, hi = 63;
    while (lo < hi) {
        const int mid = (lo + hi) >> 1;
        if (sgw[mid] <= u) lo = mid + 1; else hi = mid;
    }
    const int below = lo - 1;
    const int above = lo < 62 ? lo : 62;
    const float cbv = sgw[below], cav = sgw[above];
    float den = cav - cbv;
    if (den < 1e-5f) den = 1.f;
    const float t  = __fdividef(u - cbv, den);
    const float bb = 0.5f * (zw[below] + zw[below + 1]);
    const float ba = 0.5f * (zw[above] + zw[above + 1]);
    return fmaf(t, ba - bb, bb);
}

struct __align__(16) RayShared {
    float zw[128];    // coarse z [0..63]; sorted all-z after scatter
    float sgw[128];   // cdf [0..62]; sorted fine z [64..127]; sorted sigma after scatter
    float cw[384];    // wtw alias [0..63]; PQ alias [64..191]; sorted rgb after scatter
};

// Tiny MLP at FOUR points (2 per ray, 2 rays). h = relu(P + z*Q); out = h @ W2 + b2.
// pq arrays (shared, ulonglong2[32]): [j] = (P_pair_j, Q_pair_j), pair j = units {2j,2j+1}.
__device__ __forceinline__ void field_eval4(
    float zA0, float zA1, float zB0, float zB1,
    const ulonglong2* __restrict__ pqA, const ulonglong2* __restrict__ pqB,
    float4 b2v,
    float4& oA0, float4& oA1, float4& oB0, float4& oB1)
{
    const ulonglong2* __restrict__ w2t = cAll + 64;
    const ull ZA0 = pack2(zA0, zA0), ZA1 = pack2(zA1, zA1);
    const ull ZB0 = pack2(zB0, zB0), ZB1 = pack2(zB1, zB1);
    ull aA0c0 = pack2(b2v.x, 0.f), aA0c1 = pack2(b2v.y, 0.f), aA0c2 = pack2(b2v.z, 0.f), aA0c3 = pack2(b2v.w, 0.f);
    ull aA1c0 = aA0c0, aA1c1 = aA0c1, aA1c2 = aA0c2, aA1c3 = aA0c3;
    ull aB0c0 = aA0c0, aB0c1 = aA0c1, aB0c2 = aA0c2, aB0c3 = aA0c3;
    ull aB1c0 = aA0c0, aB1c1 = aA0c1, aB1c2 = aA0c2, aB1c3 = aA0c3;
    #pragma unroll
    for (int q = 0; q < 16; ++q) {
        const ulonglong2 pA0 = pqA[2 * q], pA1 = pqA[2 * q + 1];
        const ulonglong2 pB0 = pqB[2 * q], pB1 = pqB[2 * q + 1];
        const ull hA0a = relu2(fma2(ZA0, pA0.y, pA0.x));
        const ull hA0b = relu2(fma2(ZA0, pA1.y, pA1.x));
        const ull hA1a = relu2(fma2(ZA1, pA0.y, pA0.x));
        const ull hA1b = relu2(fma2(ZA1, pA1.y, pA1.x));
        const ull hB0a = relu2(fma2(ZB0, pB0.y, pB0.x));
        const ull hB0b = relu2(fma2(ZB0, pB1.y, pB1.x));
        const ull hB1a = relu2(fma2(ZB1, pB0.y, pB0.x));
        const ull hB1b = relu2(fma2(ZB1, pB1.y, pB1.x));
        const ulonglong2 T0 = w2t[4 * q + 0], T1 = w2t[4 * q + 1];
        const ulonglong2 T2 = w2t[4 * q + 2], T3 = w2t[4 * q + 3];
        aA0c0 = fma2(hA0a, T0.x, aA0c0); aA0c0 = fma2(hA0b, T0.y, aA0c0);
        aA0c1 = fma2(hA0a, T1.x, aA0c1); aA0c1 = fma2(hA0b, T1.y, aA0c1);
        aA0c2 = fma2(hA0a, T2.x, aA0c2); aA0c2 = fma2(hA0b, T2.y, aA0c2);
        aA0c3 = fma2(hA0a, T3.x, aA0c3); aA0c3 = fma2(hA0b, T3.y, aA0c3);
        aA1c0 = fma2(hA1a, T0.x, aA1c0); aA1c0 = fma2(hA1b, T0.y, aA1c0);
        aA1c1 = fma2(hA1a, T1.x, aA1c1); aA1c1 = fma2(hA1b, T1.y, aA1c1);
        aA1c2 = fma2(hA1a, T2.x, aA1c2); aA1c2 = fma2(hA1b, T2.y, aA1c2);
        aA1c3 = fma2(hA1a, T3.x, aA1c3); aA1c3 = fma2(hA1b, T3.y, aA1c3);
        aB0c0 = fma2(hB0a, T0.x, aB0c0); aB0c0 = fma2(hB0b, T0.y, aB0c0);
        aB0c1 = fma2(hB0a, T1.x, aB0c1); aB0c1 = fma2(hB0b, T1.y, aB0c1);
        aB0c2 = fma2(hB0a, T2.x, aB0c2); aB0c2 = fma2(hB0b, T2.y, aB0c2);
        aB0c3 = fma2(hB0a, T3.x, aB0c3); aB0c3 = fma2(hB0b, T3.y, aB0c3);
        aB1c0 = fma2(hB1a, T0.x, aB1c0); aB1c0 = fma2(hB1b, T0.y, aB1c0);
        aB1c1 = fma2(hB1a, T1.x, aB1c1); aB1c1 = fma2(hB1b, T1.y, aB1c1);
        aB1c2 = fma2(hB1a, T2.x, aB1c2); aB1c2 = fma2(hB1b, T2.y, aB1c2);
        aB1c3 = fma2(hB1a, T3.x, aB1c3); aB1c3 = fma2(hB1b, T3.y, aB1c3);
    }
    float lo, hi;
    unpack2(aA0c0, lo, hi); oA0.x = lo + hi;
    unpack2(aA0c1, lo, hi); oA0.y = sigm(lo + hi);
    unpack2(aA0c2, lo, hi); oA0.z = sigm(lo + hi);
    unpack2(aA0c3, lo, hi); oA0.w = sigm(lo + hi);
    unpack2(aA1c0, lo, hi); oA1.x = lo + hi;
    unpack2(aA1c1, lo, hi); oA1.y = sigm(lo + hi);
    unpack2(aA1c2, lo, hi); oA1.z = sigm(lo + hi);
    unpack2(aA1c3, lo, hi); oA1.w = sigm(lo + hi);
    unpack2(aB0c0, lo, hi); oB0.x = lo + hi;
    unpack2(aB0c1, lo, hi); oB0.y = sigm(lo + hi);
    unpack2(aB0c2, lo, hi); oB0.z = sigm(lo + hi);
    unpack2(aB0c3, lo, hi); oB0.w = sigm(lo + hi);
    unpack2(aB1c0, lo, hi); oB1.x = lo + hi;
    unpack2(aB1c1, lo, hi); oB1.y = sigm(lo + hi);
    unpack2(aB1c2, lo, hi); oB1.z = sigm(lo + hi);
    unpack2(aB1c3, lo, hi); oB1.w = sigm(lo + hi);
}

// final alpha compositing over 128 sorted samples (4 per lane) for one ray
__device__ __forceinline__ void composite_final(
    const float* __restrict__ zw, const float* __restrict__ sgw,
    const float* __restrict__ cw, int lane,
    float& SW, float& SZ, float& SR, float& SG, float& SB)
{
    const int p = 4 * lane;
    const float za = zw[p], zb = zw[p + 1], zc = zw[p + 2], zd = zw[p + 3];
    const float zn = (lane < 31) ? zw[p + 4] : 0.f;
    const float sa = sgw[p], sb = sgw[p + 1], sc = sgw[p + 2], sd = sgw[p + 3];
    const float dda = zb - za, ddb = zc - zb, ddc = zd - zc;
    const float ddd = (lane == 31) ? 1e10f : (zn - zd);
    const float ea = __expf(-fmaxf(sa, 0.f) * dda);
    const float eb = __expf(-fmaxf(sb, 0.f) * ddb);
    const float ec = __expf(-fmaxf(sc, 0.f) * ddc);
    const float ed = __expf(-fmaxf(sd, 0.f) * ddd);
    const float aa = 1.f - ea, ab = 1.f - eb, ac = 1.f - ec, ad = 1.f - ed;
    const float ma = 1.f - aa + 1e-10f, mb = 1.f - ab + 1e-10f;
    const float mc = 1.f - ac + 1e-10f, md = 1.f - ad + 1e-10f;
    const float q0 = ma, q1 = ma * mb, q2 = q1 * mc, q3 = q2 * md;
    float v = q3;
    #pragma unroll
    for (int off = 1; off < 32; off <<= 1) {
        float t = __shfl_up_sync(FULL, v, off);
        if (lane >= off) v *= t;
    }
    float E = __shfl_up_sync(FULL, v, 1);
    if (lane == 0) E = 1.f;
    const float wA = aa * E, wB = ab * E * q0, wC = ac * E * q1, wD = ad * E * q2;

    SW = wA + wB + wC + wD;
    SZ = wA * za + wB * zb + wC * zc + wD * zd;
    SR = wA * cw[3 * p]     + wB * cw[3 * (p + 1)]     + wC * cw[3 * (p + 2)]     + wD * cw[3 * (p + 3)];
    SG = wA * cw[3 * p + 1] + wB * cw[3 * (p + 1) + 1] + wC * cw[3 * (p + 2) + 1] + wD * cw[3 * (p + 3) + 1];
    SB = wA * cw[3 * p + 2] + wB * cw[3 * (p + 1) + 2] + wC * cw[3 * (p + 2) + 2] + wD * cw[3 * (p + 3) + 2];

    #pragma unroll
    for (int off = 16; off; off >>= 1) {
        SW += __shfl_xor_sync(FULL, SW, off);
        SZ += __shfl_xor_sync(FULL, SZ, off);
        SR += __shfl_xor_sync(FULL, SR, off);
        SG += __shfl_xor_sync(FULL, SG, off);
        SB += __shfl_xor_sync(FULL, SB, off);
    }
}

__global__ void __launch_bounds__(256, 2)
nerf_kernel(const float* __restrict__ ro,   const float* __restrict__ rdi,
            const float* __restrict__ tform, const float* __restrict__ noise,
            const float* __restrict__ usmp,
            float* __restrict__ orgb, float* __restrict__ odep, float* __restrict__ omsk)
{
    __shared__ RayShared S[16];   // 40 KB

    const int tid = threadIdx.x;
    const int wrp = tid >> 5, lane = tid & 31;
    const int rayA = (blockIdx.x * 8 + wrp) * 2;
    const int rayB = rayA + 1;
    RayShared& A = S[2 * wrp];
    RayShared& B = S[2 * wrp + 1];

    // ---- ray state ----
    const float oxA = ro[rayA * 3 + 0], oyA = ro[rayA * 3 + 1], ozA = ro[rayA * 3 + 2];
    const float oxB = ro[rayB * 3 + 0], oyB = ro[rayB * 3 + 1], ozB = ro[rayB * 3 + 2];
    float dxA = rdi[rayA * 3 + 0], dyA = rdi[rayA * 3 + 1], dzA = rdi[rayA * 3 + 2];
    float dxB = rdi[rayB * 3 + 0], dyB = rdi[rayB * 3 + 1], dzB = rdi[rayB * 3 + 2];
    {
        const float rnA = rsqrtf(dxA * dxA + dyA * dyA + dzA * dzA);
        dxA *= rnA; dyA *= rnA; dzA *= rnA;
        const float rnB = rsqrtf(dxB * dxB + dyB * dyB + dzB * dzB);
        dxB *= rnB; dyB *= rnB; dzB *= rnB;
    }

    // ---- PQ precompute (lane = unit pair; coalesced LDG from staging) ----
    {
        const ull* w1p = (const ull*)g_stage;
        const ull W1x = w1p[lane], W1y = w1p[32 + lane], W1z = w1p[64 + lane], B1 = w1p[96 + lane];
        const ull PA = fma2(pack2(oxA, oxA), W1x, fma2(pack2(oyA, oyA), W1y, fma2(pack2(ozA, ozA), W1z, B1)));
        const ull QA = fma2(pack2(dxA, dxA), W1x, fma2(pack2(dyA, dyA), W1y, mul2(pack2(dzA, dzA), W1z)));
        const ull PB = fma2(pack2(oxB, oxB), W1x, fma2(pack2(oyB, oyB), W1y, fma2(pack2(ozB, ozB), W1z, B1)));
        const ull QB = fma2(pack2(dxB, dxB), W1x, fma2(pack2(dyB, dyB), W1y, mul2(pack2(dzB, dzB), W1z)));
        ((ulonglong2*)(A.cw + 64))[lane] = make_ulonglong2(PA, QA);
        ((ulonglong2*)(B.cw + 64))[lane] = make_ulonglong2(PB, QB);
    }
    const ulonglong2* __restrict__ pqA = (const ulonglong2*)(A.cw + 64);
    const ulonglong2* __restrict__ pqB = (const ulonglong2*)(B.cw + 64);

    float b20, b21, b22, b23;
    unpack2(cAll[128].x, b20, b21);
    unpack2(cAll[128].y, b22, b23);
    const float4 b2v = make_float4(b20, b21, b22, b23);

    // ---- coarse stratified z (sorted by construction) ----
    const int i0 = 2 * lane, i1 = i0 + 1;
    const float2 nA = ((const float2*)(noise + rayA * 64))[lane];
    const float2 nB = ((const float2*)(noise + rayB * 64))[lane];
    const float zA0 = NEARF + (FARF - NEARF) * (((float)i0 + nA.x) * (1.f / 64.f));
    const float zA1 = NEARF + (FARF - NEARF) * (((float)i1 + nA.y) * (1.f / 64.f));
    const float zB0 = NEARF + (FARF - NEARF) * (((float)i0 + nB.x) * (1.f / 64.f));
    const float zB1 = NEARF + (FARF - NEARF) * (((float)i1 + nB.y) * (1.f / 64.f));
    A.zw[i0] = zA0; A.zw[i1] = zA1;
    B.zw[i0] = zB0; B.zw[i1] = zB1;
    __syncwarp();

    // ---- coarse MLP (4 points, one weight pass) ----
    float4 oA0, oA1, oB0, oB1;
    field_eval4(zA0, zA1, zB0, zB1, pqA, pqB, b2v, oA0, oA1, oB0, oB1);

    // ---- coarse compositing weights (two interleaved mult scans) ----
    {
        const float dA0 = zA1 - zA0;
        const float dB0 = zB1 - zB0;
        const float znxA = (lane < 31) ? A.zw[i1 + 1] : 0.f;
        const float znxB = (lane < 31) ? B.zw[i1 + 1] : 0.f;
        const float dA1 = (lane == 31) ? 1e10f : (znxA - zA1);
        const float dB1 = (lane == 31) ? 1e10f : (znxB - zB1);
        const float eA0 = __expf(-fmaxf(oA0.x, 0.f) * dA0);
        const float eA1 = __expf(-fmaxf(oA1.x, 0.f) * dA1);
        const float eB0 = __expf(-fmaxf(oB0.x, 0.f) * dB0);
        const float eB1 = __expf(-fmaxf(oB1.x, 0.f) * dB1);
        const float aA0 = 1.f - eA0, aA1 = 1.f - eA1;
        const float aB0 = 1.f - eB0, aB1 = 1.f - eB1;
        const float mA0 = 1.f - aA0 + 1e-10f, mA1 = 1.f - aA1 + 1e-10f;
        const float mB0 = 1.f - aB0 + 1e-10f, mB1 = 1.f - aB1 + 1e-10f;
        float vA = mA0 * mA1, vB = mB0 * mB1;
        #pragma unroll
        for (int off = 1; off < 32; off <<= 1) {
            const float tA = __shfl_up_sync(FULL, vA, off);
            const float tB = __shfl_up_sync(FULL, vB, off);
            if (lane >= off) { vA *= tA; vB *= tB; }
        }
        float exA = __shfl_up_sync(FULL, vA, 1);
        float exB = __shfl_up_sync(FULL, vB, 1);
        if (lane == 0) { exA = 1.f; exB = 1.f; }
        A.cw[i0] = aA0 * exA; A.cw[i1] = aA1 * exA * mA0;   // wtw alias
        B.cw[i0] = aB0 * exB; B.cw[i1] = aB1 * exB * mB0;
    }
    __syncwarp();

    // ---- pooled pdf -> cdf (63 entries in sgw[0..62]) for both rays ----
    {
        float s1A = 0.f, s2A = 0.f, s1B = 0.f, s2B = 0.f;
        if (lane < 31) {
            const int ii = 2 * lane + 1;
            const float wmA = A.cw[ii - 1], wcA = A.cw[ii], wpA = A.cw[ii + 1], wqA = A.cw[ii + 2];
            s1A = 0.5f * (fmaxf(wmA, wcA) + fmaxf(wcA, wpA)) + 0.01f;
            s2A = 0.5f * (fmaxf(wcA, wpA) + fmaxf(wpA, wqA)) + 0.01f;
            const float wmB = B.cw[ii - 1], wcB = B.cw[ii], wpB = B.cw[ii + 1], wqB = B.cw[ii + 2];
            s1B = 0.5f * (fmaxf(wmB, wcB) + fmaxf(wcB, wpB)) + 0.01f;
            s2B = 0.5f * (fmaxf(wcB, wpB) + fmaxf(wpB, wqB)) + 0.01f;
        }
        const float prA = s1A + s2A, prB = s1B + s2B;
        float vA = prA, vB = prB;
        #pragma unroll
        for (int off = 1; off < 32; off <<= 1) {
            const float tA = __shfl_up_sync(FULL, vA, off);
            const float tB = __shfl_up_sync(FULL, vB, off);
            if (lane >= off) { vA += tA; vB += tB; }
        }
        const float rvA = __fdividef(1.f, __shfl_sync(FULL, vA, 30));
        const float rvB = __fdividef(1.f, __shfl_sync(FULL, vB, 30));
        const float exA = vA - prA, exB = vB - prB;
        if (lane == 0) { A.sgw[0] = 0.f; B.sgw[0] = 0.f; }
        if (lane < 31) {
            A.sgw[2 * lane + 1] = (exA + s1A) * rvA;
            A.sgw[2 * lane + 2] = vA * rvA;
            B.sgw[2 * lane + 1] = (exB + s1B) * rvB;
            B.sgw[2 * lane + 2] = vB * rvB;
        }
    }
    __syncwarp();

    // ---- inverse-CDF fine samples (2 per lane per ray) ----
    float vA0, vA1, vB0, vB1;
    {
        const float* uuA = usmp + rayA * 64;
        const float* uuB = usmp + rayB * 64;
        vA0 = sample_pdf_one(A.sgw, A.zw, uuA[lane]);
        vA1 = sample_pdf_one(A.sgw, A.zw, uuA[lane + 32]);
        vB0 = sample_pdf_one(B.sgw, B.zw, uuB[lane]);
        vB1 = sample_pdf_one(B.sgw, B.zw, uuB[lane + 32]);
    }

    // ---- bitonic sort of 64 fine samples per ray (both rays interleaved) ----
    {
        const int e0l = lane, e1l = lane + 32;
        #pragma unroll
        for (int k = 2; k <= 64; k <<= 1) {
            #pragma unroll
            for (int j = k >> 1; j >= 1; j >>= 1) {
                if (j == 32) {
                    float lo = fminf(vA0, vA1), hi = fmaxf(vA0, vA1);
                    vA0 = lo; vA1 = hi;
                    lo = fminf(vB0, vB1); hi = fmaxf(vB0, vB1);
                    vB0 = lo; vB1 = hi;
                } else {
                    const bool keep0 = (((e0l & k) == 0) == ((e0l & j) == 0));
                    const bool keep1 = (((e1l & k) == 0) == ((e1l & j) == 0));
                    const float tA0 = __shfl_xor_sync(FULL, vA0, j);
                    const float tA1 = __shfl_xor_sync(FULL, vA1, j);
                    const float tB0 = __shfl_xor_sync(FULL, vB0, j);
                    const float tB1 = __shfl_xor_sync(FULL, vB1, j);
                    vA0 = keep0 ? fminf(vA0, tA0) : fmaxf(vA0, tA0);
                    vA1 = keep1 ? fminf(vA1, tA1) : fmaxf(vA1, tA1);
                    vB0 = keep0 ? fminf(vB0, tB0) : fmaxf(vB0, tB0);
                    vB1 = keep1 ? fminf(vB1, tB1) : fmaxf(vB1, tB1);
                }
            }
        }
    }
    A.sgw[64 + lane] = vA0; A.sgw[96 + lane] = vA1;   // sorted fine z
    B.sgw[64 + lane] = vB0; B.sgw[96 + lane] = vB1;

    // ---- fine MLP at SORTED positions ----
    float4 fA0, fA1, fB0, fB1;
    field_eval4(vA0, vA1, vB0, vB1, pqA, pqB, b2v, fA0, fA1, fB0, fB1);
    __syncwarp();                                      // sf fully written

    // ---- merge ranks: coarse sorted x fine sorted ----
    const int rA0 = i0 + count_lt(A.sgw + 64, zA0);
    const int rA1 = i1 + count_lt(A.sgw + 64, zA1);
    const int rA2 = lane      + count_le(A.zw, vA0);
    const int rA3 = lane + 32 + count_le(A.zw, vA1);
    const int rB0 = i0 + count_lt(B.sgw + 64, zB0);
    const int rB1 = i1 + count_lt(B.sgw + 64, zB1);
    const int rB2 = lane      + count_le(B.zw, vB0);
    const int rB3 = lane + 32 + count_le(B.zw, vB1);
    __syncwarp();                                      // all reads done before scatter

    // ---- scatter (overwrites zw/sgw/cw; PQ & wtw are dead) ----
    A.zw[rA0] = zA0; A.sgw[rA0] = oA0.x; A.cw[3 * rA0] = oA0.y; A.cw[3 * rA0 + 1] = oA0.z; A.cw[3 * rA0 + 2] = oA0.w;
    A.zw[rA1] = zA1; A.sgw[rA1] = oA1.x; A.cw[3 * rA1] = oA1.y; A.cw[3 * rA1 + 1] = oA1.z; A.cw[3 * rA1 + 2] = oA1.w;
    A.zw[rA2] = vA0; A.sgw[rA2] = fA0.x; A.cw[3 * rA2] = fA0.y; A.cw[3 * rA2 + 1] = fA0.z; A.cw[3 * rA2 + 2] = fA0.w;
    A.zw[rA3] = vA1; A.sgw[rA3] = fA1.x; A.cw[3 * rA3] = fA1.y; A.cw[3 * rA3 + 1] = fA1.z; A.cw[3 * rA3 + 2] = fA1.w;
    B.zw[rB0] = zB0; B.sgw[rB0] = oB0.x; B.cw[3 * rB0] = oB0.y; B.cw[3 * rB0 + 1] = oB0.z; B.cw[3 * rB0 + 2] = oB0.w;
    B.zw[rB1] = zB1; B.sgw[rB1] = oB1.x; B.cw[3 * rB1] = oB1.y; B.cw[3 * rB1 + 1] = oB1.z; B.cw[3 * rB1 + 2] = oB1.w;
    B.zw[rB2] = vB0; B.sgw[rB2] = fB0.x; B.cw[3 * rB2] = fB0.y; B.cw[3 * rB2 + 1] = fB0.z; B.cw[3 * rB2 + 2] = fB0.w;
    B.zw[rB3] = vB1; B.sgw[rB3] = fB1.x; B.cw[3 * rB3] = fB1.y; B.cw[3 * rB3 + 1] = fB1.z; B.cw[3 * rB3 + 2] = fB1.w;
    __syncwarp();

    // ---- final compositing, both rays ----
    float SWA, SZA, SRA, SGA, SBA, SWB, SZB, SRB, SGB, SBB;
    composite_final(A.zw, A.sgw, A.cw, lane, SWA, SZA, SRA, SGA, SBA);
    composite_final(B.zw, B.sgw, B.cw, lane, SWB, SZB, SRB, SGB, SBB);

    if (lane == 0) {
        orgb[rayA * 3 + 0] = SRA;
        orgb[rayA * 3 + 1] = SGA;
        orgb[rayA * 3 + 2] = SBA;
        const float* Tm = tform + (rayA >> 12) * 16;
        const float vz = dxA * Tm[2] + dyA * Tm[6] + dzA * Tm[10];
        odep[rayA] = -vz * SZA;
        omsk[rayA] = SWA;
    }
    if (lane == 1) {
        orgb[rayB * 3 + 0] = SRB;
        orgb[rayB * 3 + 1] = SGB;
        orgb[rayB * 3 + 2] = SBB;
        const float* Tm = tform + (rayB >> 12) * 16;
        const float vz = dxB * Tm[2] + dyB * Tm[6] + dzB * Tm[10];
        odep[rayB] = -vz * SZB;
        omsk[rayB] = SWB;
    }
}

extern "C" void kernel_launch(void* const* d_in, const int* in_sizes, int n_in,
                              void* d_out, int out_size)
{
    const float* ro    = (const float*)d_in[0];
    const float* rdi   = (const float*)d_in[1];
    const float* tform = (const float*)d_in[2];
    const float* noise = (const float*)d_in[3];
    const float* usmp  = (const float*)d_in[4];
    const float* W1    = (const float*)d_in[5];
    const float* b1    = (const float*)d_in[6];
    const float* W2    = (const float*)d_in[7];
    const float* b2    = (const float*)d_in[8];

    float* out = (float*)d_out;
    float* orgb = out;
    float* odep = out + RAYS_TOTAL * 3;
    float* omsk = odep + RAYS_TOTAL;

    pack_weights<<<1, 64>>>(W1, b1, W2, b2);
    void* stage_addr = nullptr;
    cudaGetSymbolAddress(&stage_addr, g_stage);
    cudaMemcpyToSymbolAsync(cAll, stage_addr, sizeof(g_stage), 0,
                            cudaMemcpyDeviceToDevice, 0);

    dim3 grid(RAYS_TOTAL / 16);   // 1024 blocks, 2 rays per warp, 8 warps/block
    dim3 block(256);
    nerf_kernel<<<grid, block>>>(ro, rdi, tform, noise, usmp, orgb, odep, omsk);
}

// round 7
// speedup vs baseline: 2.0806x; 1.0860x over previous
#include <cuda_runtime.h>

#define FULL 0xffffffffu
typedef unsigned long long ull;

constexpr int   RAYS_TOTAL = 16384;
constexpr float NEARF = 2.0f, FARF = 6.0f;
constexpr int   RPB = 8;   // rays (warps) per block

__device__ __forceinline__ ull pack2(float lo, float hi) {
    ull r; asm("mov.b64 %0,{%1,%2};" : "=l"(r) : "f"(lo), "f"(hi)); return r;
}
__device__ __forceinline__ void unpack2(ull v, float& lo, float& hi) {
    asm("mov.b64 {%0,%1},%2;" : "=f"(lo), "=f"(hi) : "l"(v));
}
__device__ __forceinline__ ull fma2(ull a, ull b, ull c) {
    ull d; asm("fma.rn.f32x2 %0,%1,%2,%3;" : "=l"(d) : "l"(a), "l"(b), "l"(c)); return d;
}
__device__ __forceinline__ ull mul2(ull a, ull b) {
    ull d; asm("mul.rn.f32x2 %0,%1,%2;" : "=l"(d) : "l"(a), "l"(b)); return d;
}
__device__ __forceinline__ ull relu2(ull v) {
    float lo, hi; unpack2(v, lo, hi);
    return pack2(fmaxf(lo, 0.f), fmaxf(hi, 0.f));
}
__device__ __forceinline__ float sigm(float x) {
    return __fdividef(1.f, 1.f + __expf(-x));
}

// ---- weights ----
// g_stage layout (coalesced LDG source for PQ precompute):
//   ull[0..31]    W1 row-x pairs (pair j = units 2j,2j+1)
//   ull[32..63]   W1 row-y pairs
//   ull[64..95]   W1 row-z pairs
//   ull[96..127]  b1 pairs
//   ull[128..255] w2t: entry e: ent=e>>1(=4q+c), half=e&1, u0=4q+2*half -> pack(W2[u0][c],W2[u0+1][c])
//   float[512..515] b2
// cAll mirrors g_stage; kernel uses cAll[64..128] (w2t + b2) via the LDC port.
__constant__ ulonglong2 cAll[129];
__device__   ulonglong2 g_stage[129];

__global__ void pack_weights(const float* __restrict__ W1, const float* __restrict__ b1f,
                             const float* __restrict__ W2, const float* __restrict__ b2f)
{
    const int t = threadIdx.x;   // 0..63
    float* s = (float*)g_stage;
    s[t]       = W1[t];
    s[64 + t]  = W1[64 + t];
    s[128 + t] = W1[128 + t];
    s[192 + t] = b1f[t];
    ull* w2t = ((ull*)g_stage) + 128;
    int e = t;
    #pragma unroll
    for (int k = 0; k < 2; ++k, e += 64) {
        const int ent = e >> 1, half = e & 1;
        const int q = ent >> 2, c = ent & 3;
        const int u0 = 4 * q + 2 * half;
        w2t[e] = pack2(W2[u0 * 4 + c], W2[(u0 + 1) * 4 + c]);
    }
    if (t == 0) {
        s[512] = b2f[0]; s[513] = b2f[1]; s[514] = b2f[2]; s[515] = b2f[3];
    }
}

// # elements < x in sorted a[0..63]
__device__ __forceinline__ int count_lt(const float* __restrict__ a, float x) {
    int lo = 0, hi = 64;
    #pragma unroll
    for (int it = 0; it < 7; ++it) {
        if (lo < hi) { int m = (lo + hi) >> 1; if (a[m] < x) lo = m + 1; else hi = m; }
    }
    return lo;
}
// # elements <= x in sorted a[0..63]
__device__ __forceinline__ int count_le(const float* __restrict__ a, float x) {
    int lo = 0, hi = 64;
    #pragma unroll
    for (int it = 0; it < 7; ++it) {
        if (lo < hi) { int m = (lo + hi) >> 1; if (a[m] <= x) lo = m + 1; else hi = m; }
    }
    return lo;
}

// Tiny MLP at TWO points of one ray, layer-1 folded: h = relu(P + z*Q).
// pq (shared, ulonglong2[32]): [j] = (P_pair_j, Q_pair_j), pair j = units {2j,2j+1}.
// Layer-2 weights from __constant__ (LDC warp-broadcast).
__device__ __forceinline__ void field_eval2(
    float z0, float z1,
    const ulonglong2* __restrict__ pq, float4 b2v,
    float4& o0, float4& o1)
{
    const ulonglong2* __restrict__ w2t = cAll + 64;
    const ull Z0 = pack2(z0, z0), Z1 = pack2(z1, z1);
    ull a00 = pack2(b2v.x, 0.f), a01 = pack2(b2v.y, 0.f);
    ull a02 = pack2(b2v.z, 0.f), a03 = pack2(b2v.w, 0.f);
    ull a10 = a00, a11 = a01, a12 = a02, a13 = a03;
    #pragma unroll
    for (int q = 0; q < 16; ++q) {
        const ulonglong2 p0 = pq[2 * q], p1 = pq[2 * q + 1];
        const ull h0a = relu2(fma2(Z0, p0.y, p0.x));
        const ull h0b = relu2(fma2(Z0, p1.y, p1.x));
        const ull h1a = relu2(fma2(Z1, p0.y, p0.x));
        const ull h1b = relu2(fma2(Z1, p1.y, p1.x));
        const ulonglong2 T0 = w2t[4 * q + 0], T1 = w2t[4 * q + 1];
        const ulonglong2 T2 = w2t[4 * q + 2], T3 = w2t[4 * q + 3];
        a00 = fma2(h0a, T0.x, a00); a00 = fma2(h0b, T0.y, a00);
        a01 = fma2(h0a, T1.x, a01); a01 = fma2(h0b, T1.y, a01);
        a02 = fma2(h0a, T2.x, a02); a02 = fma2(h0b, T2.y, a02);
        a03 = fma2(h0a, T3.x, a03); a03 = fma2(h0b, T3.y, a03);
        a10 = fma2(h1a, T0.x, a10); a10 = fma2(h1b, T0.y, a10);
        a11 = fma2(h1a, T1.x, a11); a11 = fma2(h1b, T1.y, a11);
        a12 = fma2(h1a, T2.x, a12); a12 = fma2(h1b, T2.y, a12);
        a13 = fma2(h1a, T3.x, a13); a13 = fma2(h1b, T3.y, a13);
    }
    float lo, hi;
    unpack2(a00, lo, hi); o0.x = lo + hi;
    unpack2(a01, lo, hi); o0.y = sigm(lo + hi);
    unpack2(a02, lo, hi); o0.z = sigm(lo + hi);
    unpack2(a03, lo, hi); o0.w = sigm(lo + hi);
    unpack2(a10, lo, hi); o1.x = lo + hi;
    unpack2(a11, lo, hi); o1.y = sigm(lo + hi);
    unpack2(a12, lo, hi); o1.z = sigm(lo + hi);
    unpack2(a13, lo, hi); o1.w = sigm(lo + hi);
}

__global__ void __launch_bounds__(RPB * 32, 4)
nerf_kernel(const float* __restrict__ ro,   const float* __restrict__ rdi,
            const float* __restrict__ tform, const float* __restrict__ noise,
            const float* __restrict__ usmp,
            float* __restrict__ orgb, float* __restrict__ odep, float* __restrict__ omsk)
{
    __shared__ float  sZ [RPB][128];   // coarse z [0..63]; sorted all-z after scatter
    __shared__ float  sSg[RPB][128];   // cdf [0..62], sorted fine z [64..127]; sorted sigma after scatter
    __shared__ float  sC [RPB][384];   // PQ alias [64..191]; sorted rgb after scatter
    __shared__ float  sWt[RPB][64];    // coarse compositing weights

    const int tid = threadIdx.x;
    const int wrp = tid >> 5, lane = tid & 31;
    const int ray = blockIdx.x * RPB + wrp;
    float* zw  = sZ[wrp];
    float* sgw = sSg[wrp];
    float* sf  = sgw + 64;     // sorted fine z
    float* cw  = sC[wrp];
    float* wtw = sWt[wrp];

    const int bidx = ray >> 12;

    const float ox = ro[ray * 3 + 0], oy = ro[ray * 3 + 1], oz = ro[ray * 3 + 2];
    float dx = rdi[ray * 3 + 0], dy = rdi[ray * 3 + 1], dz = rdi[ray * 3 + 2];
    const float rinvn = rsqrtf(dx * dx + dy * dy + dz * dz);
    dx *= rinvn; dy *= rinvn; dz *= rinvn;

    // ---- PQ precompute (lane = unit pair; coalesced LDG from staging) ----
    {
        const ull* w1p = (const ull*)g_stage;
        const ull W1x = w1p[lane], W1y = w1p[32 + lane], W1z = w1p[64 + lane], B1 = w1p[96 + lane];
        const ull P = fma2(pack2(ox, ox), W1x, fma2(pack2(oy, oy), W1y, fma2(pack2(oz, oz), W1z, B1)));
        const ull Q = fma2(pack2(dx, dx), W1x, fma2(pack2(dy, dy), W1y, mul2(pack2(dz, dz), W1z)));
        ((ulonglong2*)(cw + 64))[lane] = make_ulonglong2(P, Q);
    }
    const ulonglong2* __restrict__ pq = (const ulonglong2*)(cw + 64);

    float b20, b21, b22, b23;
    unpack2(cAll[128].x, b20, b21);
    unpack2(cAll[128].y, b22, b23);
    const float4 b2v = make_float4(b20, b21, b22, b23);

    // ---- coarse stratified z (sorted by construction) ----
    const float2 nzp = ((const float2*)(noise + ray * 64))[lane];
    const int i0 = 2 * lane, i1 = i0 + 1;
    const float z0 = NEARF + (FARF - NEARF) * (((float)i0 + nzp.x) * (1.f / 64.f));
    const float z1 = NEARF + (FARF - NEARF) * (((float)i1 + nzp.y) * (1.f / 64.f));
    zw[i0] = z0; zw[i1] = z1;
    __syncwarp();

    // ---- coarse MLP ----
    float4 o0, o1;
    field_eval2(z0, z1, pq, b2v, o0, o1);

    // ---- coarse compositing weights (warp multiplicative scan) ----
    {
        const float d0 = z1 - z0;
        const float znx = (lane < 31) ? zw[i1 + 1] : 0.f;
        const float d1 = (lane == 31) ? 1e10f : (znx - z1);
        const float e0 = __expf(-fmaxf(o0.x, 0.f) * d0);
        const float e1 = __expf(-fmaxf(o1.x, 0.f) * d1);
        const float a0 = 1.f - e0, a1 = 1.f - e1;
        const float m0 = 1.f - a0 + 1e-10f, m1 = 1.f - a1 + 1e-10f;
        float v = m0 * m1;
        #pragma unroll
        for (int off = 1; off < 32; off <<= 1) {
            float t = __shfl_up_sync(FULL, v, off);
            if (lane >= off) v *= t;
        }
        float ex = __shfl_up_sync(FULL, v, 1);
        if (lane == 0) ex = 1.f;
        wtw[i0] = a0 * ex;
        wtw[i1] = a1 * ex * m0;
    }
    __syncwarp();

    // ---- pooled pdf -> cdf (63 entries in sgw[0..62]) ----
    {
        float s1 = 0.f, s2 = 0.f;
        if (lane < 31) {
            const int ii = 2 * lane + 1;
            const float wm = wtw[ii - 1], wc = wtw[ii], wp = wtw[ii + 1], wq = wtw[ii + 2];
            s1 = 0.5f * (fmaxf(wm, wc) + fmaxf(wc, wp)) + 0.01f;
            s2 = 0.5f * (fmaxf(wc, wp) + fmaxf(wp, wq)) + 0.01f;
        }
        const float pr = s1 + s2;
        float v = pr;
        #pragma unroll
        for (int off = 1; off < 32; off <<= 1) {
            float t = __shfl_up_sync(FULL, v, off);
            if (lane >= off) v += t;
        }
        const float tot = __shfl_sync(FULL, v, 30);
        const float rv = __fdividef(1.f, tot);
        const float ex = v - pr;
        if (lane == 0) sgw[0] = 0.f;
        if (lane < 31) {
            sgw[2 * lane + 1] = (ex + s1) * rv;
            sgw[2 * lane + 2] = v * rv;
        }
    }
    __syncwarp();

    // ---- inverse-CDF fine samples (2 per lane, unsorted) ----
    const float* uu = usmp + ray * 64;
    float zs0 = 0.f, zs1 = 0.f;
    #pragma unroll
    for (int k = 0; k < 2; ++k) {
        const float u = uu[lane + 32 * k];
        int lo = 0, hi = 63;
        while (lo < hi) {
            const int mid = (lo + hi) >> 1;
            if (sgw[mid] <= u) lo = mid + 1; else hi = mid;
        }
        const int below = lo - 1;
        const int above = lo < 62 ? lo : 62;
        const float cbv = sgw[below], cav = sgw[above];
        float den = cav - cbv;
        if (den < 1e-5f) den = 1.f;
        const float t  = __fdividef(u - cbv, den);
        const float bb = 0.5f * (zw[below] + zw[below + 1]);
        const float ba = 0.5f * (zw[above] + zw[above + 1]);
        const float zz = fmaf(t, ba - bb, bb);
        if (k == 0) zs0 = zz; else zs1 = zz;
    }

    // ---- bitonic sort of the 64 fine samples (registers + shfl) ----
    float v0 = zs0, v1 = zs1;
    {
        const int e0l = lane, e1l = lane + 32;
        #pragma unroll
        for (int k = 2; k <= 64; k <<= 1) {
            #pragma unroll
            for (int j = k >> 1; j >= 1; j >>= 1) {
                if (j == 32) {
                    const float lo = fminf(v0, v1), hi = fmaxf(v0, v1);
                    v0 = lo; v1 = hi;
                } else {
                    const float t0 = __shfl_xor_sync(FULL, v0, j);
                    const bool keep0 = (((e0l & k) == 0) == ((e0l & j) == 0));
                    v0 = keep0 ? fminf(v0, t0) : fmaxf(v0, t0);
                    const float t1 = __shfl_xor_sync(FULL, v1, j);
                    const bool keep1 = (((e1l & k) == 0) == ((e1l & j) == 0));
                    v1 = keep1 ? fminf(v1, t1) : fmaxf(v1, t1);
                }
            }
        }
    }
    __syncwarp();                                  // cdf reads done before sf write
    sf[lane] = v0;
    sf[lane + 32] = v1;

    // ---- fine MLP at SORTED fine positions ----
    float4 f0, f1;
    field_eval2(v0, v1, pq, b2v, f0, f1);
    __syncwarp();                                  // sf fully written

    // ---- merge ranks: coarse sorted x fine sorted ----
    const int r0 = i0 + count_lt(sf, z0);          // ties: coarse first
    const int r1 = i1 + count_lt(sf, z1);
    const int r2 = lane      + count_le(zw, v0);   // ties: fine after coarse
    const int r3 = lane + 32 + count_le(zw, v1);
    __syncwarp();                                  // all reads (incl. PQ) done before scatter

    zw[r0] = z0; sgw[r0] = o0.x; cw[3 * r0] = o0.y; cw[3 * r0 + 1] = o0.z; cw[3 * r0 + 2] = o0.w;
    zw[r1] = z1; sgw[r1] = o1.x; cw[3 * r1] = o1.y; cw[3 * r1 + 1] = o1.z; cw[3 * r1 + 2] = o1.w;
    zw[r2] = v0; sgw[r2] = f0.x; cw[3 * r2] = f0.y; cw[3 * r2 + 1] = f0.z; cw[3 * r2 + 2] = f0.w;
    zw[r3] = v1; sgw[r3] = f1.x; cw[3 * r3] = f1.y; cw[3 * r3 + 1] = f1.z; cw[3 * r3 + 2] = f1.w;
    __syncwarp();

    // ---- final compositing over 128 sorted samples (4 per lane) ----
    const int p = 4 * lane;
    const float za = zw[p], zb = zw[p + 1], zc = zw[p + 2], zd = zw[p + 3];
    const float zn = (lane < 31) ? zw[p + 4] : 0.f;
    const float sa = sgw[p], sb = sgw[p + 1], sc = sgw[p + 2], sd = sgw[p + 3];
    const float dda = zb - za, ddb = zc - zb, ddc = zd - zc;
    const float ddd = (lane == 31) ? 1e10f : (zn - zd);
    const float ea = __expf(-fmaxf(sa, 0.f) * dda);
    const float eb = __expf(-fmaxf(sb, 0.f) * ddb);
    const float ec = __expf(-fmaxf(sc, 0.f) * ddc);
    const float ed = __expf(-fmaxf(sd, 0.f) * ddd);
    const float aa = 1.f - ea, ab = 1.f - eb, ac = 1.f - ec, ad = 1.f - ed;
    const float ma = 1.f - aa + 1e-10f, mb = 1.f - ab + 1e-10f;
    const float mc = 1.f - ac + 1e-10f, md = 1.f - ad + 1e-10f;
    const float q0 = ma, q1 = ma * mb, q2 = q1 * mc, q3 = q2 * md;
    float v = q3;
    #pragma unroll
    for (int off = 1; off < 32; off <<= 1) {
        float t = __shfl_up_sync(FULL, v, off);
        if (lane >= off) v *= t;
    }
    float E = __shfl_up_sync(FULL, v, 1);
    if (lane == 0) E = 1.f;
    const float wA = aa * E, wB = ab * E * q0, wC = ac * E * q1, wD = ad * E * q2;

    float SW = wA + wB + wC + wD;
    float SZ = wA * za + wB * zb + wC * zc + wD * zd;
    float SR = wA * cw[3 * p]     + wB * cw[3 * (p + 1)]     + wC * cw[3 * (p + 2)]     + wD * cw[3 * (p + 3)];
    float SG = wA * cw[3 * p + 1] + wB * cw[3 * (p + 1) + 1] + wC * cw[3 * (p + 2) + 1] + wD * cw[3 * (p + 3) + 1];
    float SB = wA * cw[3 * p + 2] + wB * cw[3 * (p + 1) + 2] + wC * cw[3 * (p + 2) + 2] + wD * cw[3 * (p + 3) + 2];

    #pragma unroll
    for (int off = 16; off; off >>= 1) {
        SW += __shfl_xor_sync(FULL, SW, off);
        SZ += __shfl_xor_sync(FULL, SZ, off);
        SR += __shfl_xor_sync(FULL, SR, off);
        SG += __shfl_xor_sync(FULL, SG, off);
        SB += __shfl_xor_sync(FULL, SB, off);
    }

    if (lane == 0) {
        orgb[ray * 3 + 0] = SR;
        orgb[ray * 3 + 1] = SG;
        orgb[ray * 3 + 2] = SB;
        const float* Tm = tform + bidx * 16;
        const float vz = dx * Tm[2] + dy * Tm[6] + dz * Tm[10];
        odep[ray] = -vz * SZ;
        omsk[ray] = SW;
    }
}

extern "C" void kernel_launch(void* const* d_in, const int* in_sizes, int n_in,
                              void* d_out, int out_size)
{
    const float* ro    = (const float*)d_in[0];
    const float* rdi   = (const float*)d_in[1];
    const float* tform = (const float*)d_in[2];
    const float* noise = (const float*)d_in[3];
    const float* usmp  = (const float*)d_in[4];
    const float* W1    = (const float*)d_in[5];
    const float* b1    = (const float*)d_in[6];
    const float* W2    = (const float*)d_in[7];
    const float* b2    = (const float*)d_in[8];

    float* out = (float*)d_out;
    float* orgb = out;
    float* odep = out + RAYS_TOTAL * 3;
    float* omsk = odep + RAYS_TOTAL;

    pack_weights<<<1, 64>>>(W1, b1, W2, b2);
    void* stage_addr = nullptr;
    cudaGetSymbolAddress(&stage_addr, g_stage);
    cudaMemcpyToSymbolAsync(cAll, stage_addr, sizeof(g_stage), 0,
                            cudaMemcpyDeviceToDevice, 0);

    dim3 grid(RAYS_TOTAL / RPB);   // 2048 blocks, 1 ray per warp
    dim3 block(RPB * 32);
    nerf_kernel<<<grid, block>>>(ro, rdi, tform, noise, usmp, orgb, odep, omsk);
}